// round 13
// baseline (speedup 1.0000x reference)
#include <cuda_runtime.h>
#include <math.h>

#define BB    32
#define TT    128
#define IFACE 471
#define EPSF  1e-6f
#define NBLK  128
#define NTHR  1024

// ---------------- smem layout (float offsets) ----------------
#define SM_M      0        // 128x65  persistent (blocks<32)
#define SM_L      8320     // 128x129 persistent
#define SM_WRP    24832    // 512 wr  persistent
#define SM_USAGE  25344    // 128
#define SM_PREC   25472    // 128
#define SM_WW     25600    // 128
#define SM_SCR    25728    // 21120 scratch
#define SCR_FLOATS 21120
#define SM_TOTAL  (SM_SCR + SCR_FLOATS)
#define SMEM_BYTES (SM_TOTAL*4)
#define DS        16896    // D-scratch offset inside scr (x-prestage region is [0,16896))

// ---------------- device globals ----------------
__device__ float g_h[2][BB*512];
__device__ float g_reads[2][BB*256];
__device__ float g_v[BB*480];
__device__ unsigned g_flags[NBLK];   // distributed barrier flags (monotonic, replay-safe)

__device__ __forceinline__ float sigm(float x){ return 1.f/(1.f+expf(-x)); }
__device__ __forceinline__ float softplusf(float x){
    return (x>0.f) ? x+log1pf(expf(-x)) : log1pf(expf(x));
}
__device__ __forceinline__ float wredsum(float v){
    #pragma unroll
    for (int d=16; d; d>>=1) v += __shfl_xor_sync(0xffffffffu, v, d);
    return v;
}

// distributed-flag grid barrier: each block writes its own flag (no atomic
// contention), warp 0 polls all 128 flags (4 per lane). Generation-counted,
// wrap-safe, replay-safe (flags never reset; base re-read each launch).
__device__ __forceinline__ void gsync(unsigned& gen, unsigned base) {
    __syncthreads();
    gen++;
    if (threadIdx.x < 32) {
        const unsigned target = base + gen;
        if (threadIdx.x == 0) {
            __threadfence();
            atomicExch(&g_flags[blockIdx.x], target);
        }
        volatile unsigned* f = (volatile unsigned*)&g_flags[threadIdx.x*4];
        for (;;) {
            bool ok = ((int)(f[0]-target) >= 0) & ((int)(f[1]-target) >= 0)
                    & ((int)(f[2]-target) >= 0) & ((int)(f[3]-target) >= 0);
            if (__all_sync(0xffffffffu, ok)) break;
        }
        __threadfence();
    }
    __syncthreads();
}

// ---------------- out GEMM: 64 blocks (obq 0..63), 8 cols each ----------------
__device__ __forceinline__ void out_dev(const float* __restrict__ Wout,
                                        const float* __restrict__ bout,
                                        float* __restrict__ out,
                                        const float* __restrict__ hsrc,
                                        const float* __restrict__ rsrc,
                                        int tout, int obq, float* scr)
{
    const int tid = threadIdx.x;
    const int wid = tid>>5, lane = tid&31;
    const int g = tid>>7, u = tid&127, b = u&31, uc = u>>5;
    float a0 = 0.f, a1 = 0.f;
    for (int hh = 0; hh < 2; hh++) {
        {   // stage [reads,h] transposed: warp w owns batch w (segmented)
            int bb = wid;
            if (hh == 0) {
                for (int kk = lane; kk < 256; kk += 32)
                    scr[kk*33 + bb] = rsrc[bb*256 + kk];
                for (int kk = 256+lane; kk < 384; kk += 32)
                    scr[kk*33 + bb] = hsrc[bb*512 + (kk-256)];
            } else {
                for (int kk = lane; kk < 384; kk += 32)
                    scr[kk*33 + bb] = hsrc[bb*512 + 128 + kk];
            }
        }
        __syncthreads();
        int kb = g*48;
        const float* Wp = Wout + (size_t)(hh*384 + kb)*512 + obq*8 + uc*2;
        #pragma unroll 8
        for (int kk = 0; kk < 48; kk++) {
            float a = scr[(kb+kk)*33 + b];
            float2 w = *(const float2*)Wp; Wp += 512;
            a0 += a*w.x; a1 += a*w.y;
        }
        __syncthreads();
    }
    float* zbo = scr;   // sT dead
    zbo[g*256 + (uc*2  )*32 + b] = a0;
    zbo[g*256 + (uc*2+1)*32 + b] = a1;
    __syncthreads();
    if (tid < 256) {
        int b2 = tid&31, co = tid>>5;
        int col = obq*8 + co;
        float o = bout[col];
        #pragma unroll
        for (int gg = 0; gg < 8; gg++) o += zbo[gg*256 + co*32 + b2];
        out[((size_t)b2*TT + tout)*512 + col] = o;
    }
    __syncthreads();
}

// ---------------- persistent DNC kernel ----------------
__global__ void __launch_bounds__(NTHR, 1)
dnc_kernel(const float* __restrict__ xseq, const float* __restrict__ Wx,
           const float* __restrict__ Wh,   const float* __restrict__ bl,
           const float* __restrict__ Wif,  const float* __restrict__ bif,
           const float* __restrict__ Wout, const float* __restrict__ bout,
           float* __restrict__ out)
{
    extern __shared__ float sm[];
    const int tid = threadIdx.x;
    const int bq  = blockIdx.x;
    const int wid = tid>>5, lane = tid&31;
    float* scr = sm + SM_SCR;

    // barrier generation base: own flag's value from previous run (uniform
    // across blocks — every block writes its flag the same number of times)
    const unsigned barbase = *(volatile unsigned*)&g_flags[bq];
    unsigned bargen = 0;

    // ---------- init ----------
    for (int i = bq*NTHR + tid; i < BB*512; i += NBLK*NTHR) g_h[0][i] = 0.f;
    for (int i = bq*NTHR + tid; i < BB*256; i += NBLK*NTHR) g_reads[0][i] = 0.f;
    if (bq < 32)
        for (int i = tid; i < SM_SCR; i += NTHR) sm[i] = 0.f;
    // prestage x(0) transposed: warp w owns batch w
    {
        int bb = wid;
        for (int kk = lane; kk < 512; kk += 32)
            scr[kk*33 + bb] = xseq[((size_t)bb*TT + 0)*512 + kk];
    }
    float c_reg = 0.f;   // c for (b=tid&31, j=bq*4+(tid>>5)) when tid<128
    gsync(bargen, barbase);

    for (int t = 0; t < TT; t++) {
        const int p = t & 1;
        const float* hprev = g_h[p];
        float* hnew = g_h[p^1];
        const float* rdold = g_reads[p];

        // ========== phase A: LSTM z (16-way K-split, 2b x 4c regs) ==========
        {
            const int g = tid>>6, u = tid&63, bh = u&15, uc = u>>4;
            const int bw_ = wid;
            const int coff = uc*512 + bq*4;
            float acc[8] = {0,0,0,0,0,0,0,0};
            // half0: x rows [0,512) prestaged; stage reads rows [512,640)
            for (int kk = 512+lane; kk < 640; kk += 32)
                scr[kk*33 + bw_] = rdold[bw_*256 + (kk-512)];
            __syncthreads();
            {
                const int kb = g*40;
                const float* Wp = Wx + (size_t)kb*2048 + coff;
                #pragma unroll 8
                for (int kk = 0; kk < 40; kk++) {
                    float4 w = *(const float4*)Wp; Wp += 2048;
                    float a0 = scr[(kb+kk)*33 + bh];
                    float a1 = scr[(kb+kk)*33 + bh + 16];
                    acc[0]+=a0*w.x; acc[1]+=a0*w.y; acc[2]+=a0*w.z; acc[3]+=a0*w.w;
                    acc[4]+=a1*w.x; acc[5]+=a1*w.y; acc[6]+=a1*w.z; acc[7]+=a1*w.w;
                }
            }
            __syncthreads();
            // half1: rows [0,128)=reads[128,256), rows [128,640)=h
            for (int kk = lane; kk < 128; kk += 32)
                scr[kk*33 + bw_] = rdold[bw_*256 + 128 + kk];
            for (int kk = 128+lane; kk < 640; kk += 32)
                scr[kk*33 + bw_] = hprev[bw_*512 + (kk-128)];
            __syncthreads();
            {
                const int lo = g*40, hi = lo+40;
                const int mid = (lo >= 128) ? lo : (hi <= 128 ? hi : 128);
                const float* Wp = Wx + (size_t)(640+lo)*2048 + coff;
                #pragma unroll 8
                for (int kk = lo; kk < mid; kk++) {
                    float4 w = *(const float4*)Wp; Wp += 2048;
                    float a0 = scr[kk*33 + bh], a1 = scr[kk*33 + bh + 16];
                    acc[0]+=a0*w.x; acc[1]+=a0*w.y; acc[2]+=a0*w.z; acc[3]+=a0*w.w;
                    acc[4]+=a1*w.x; acc[5]+=a1*w.y; acc[6]+=a1*w.z; acc[7]+=a1*w.w;
                }
                Wp = Wh + (size_t)(mid-128)*2048 + coff;
                #pragma unroll 8
                for (int kk = mid; kk < hi; kk++) {
                    float4 w = *(const float4*)Wp; Wp += 2048;
                    float a0 = scr[kk*33 + bh], a1 = scr[kk*33 + bh + 16];
                    acc[0]+=a0*w.x; acc[1]+=a0*w.y; acc[2]+=a0*w.z; acc[3]+=a0*w.w;
                    acc[4]+=a1*w.x; acc[5]+=a1*w.y; acc[6]+=a1*w.z; acc[7]+=a1*w.w;
                }
            }
            __syncthreads();
            float* zb = scr;           // sT dead
            #pragma unroll
            for (int ci = 0; ci < 4; ci++) {
                zb[g*512 + (uc*4+ci)*32 + bh     ] = acc[ci];
                zb[g*512 + (uc*4+ci)*32 + bh + 16] = acc[4+ci];
            }
            __syncthreads();
            float* zsum = scr + 8192;
            if (tid < 512) {
                float s = 0.f;
                #pragma unroll
                for (int gg = 0; gg < 16; gg++) s += zb[gg*512 + tid];
                zsum[tid] = s;
            }
            __syncthreads();
            if (tid < 128) {
                int b = tid & 31, jj = tid >> 5;
                int j = bq*4 + jj;
                float zi = bl[       j] + zsum[(0*4+jj)*32 + b];
                float zf = bl[512  + j] + zsum[(1*4+jj)*32 + b];
                float zg = bl[1024 + j] + zsum[(2*4+jj)*32 + b];
                float zo = bl[1536 + j] + zsum[(3*4+jj)*32 + b];
                float ig = sigm(zi), fg = sigm(zf);
                float gg = tanhf(zg), og = sigm(zo);
                c_reg = fg*c_reg + ig*gg;
                hnew[b*512 + j] = og * tanhf(c_reg);
            }
        }
        gsync(bargen, barbase);

        // ========== phase C: iface v = h @ W_iface + b_iface ==========
        if (bq < 118) {
            {   // stage h^T
                int b = wid;
                for (int kk = lane; kk < 512; kk += 32)
                    scr[kk*33 + b] = hnew[b*512 + kk];
            }
            __syncthreads();
            const int g = tid>>7, u = tid&127, b = u&31, uc = u>>5;
            const int col = bq*4 + uc;
            float a = 0.f;
            if (col < IFACE) {
                const float* Wp = Wif + (size_t)(g*64)*IFACE + col;
                #pragma unroll 8
                for (int kk = 0; kk < 64; kk++) {
                    a += scr[(g*64+kk)*33 + b] * (*Wp);
                    Wp += IFACE;
                }
            }
            float* zbi = scr + DS;
            zbi[g*128 + uc*32 + b] = a;
            __syncthreads();
            if (tid < 128) {
                int b2 = tid&31, co = tid>>5;
                int c2 = bq*4 + co;
                if (c2 < IFACE) {
                    float v = bif[c2];
                    #pragma unroll
                    for (int gg = 0; gg < 8; gg++) v += zbi[gg*128 + co*32 + b2];
                    g_v[b2*480 + c2] = v;
                }
            }
        }
        gsync(bargen, barbase);

        // ========== slot 3: D (blocks 0-31) || out(t-1) (32-95) || idle ======
        if (bq < 32) {
            const int b = bq;
            float* sM  = sm + SM_M;     float* sL  = sm + SM_L;
            float* sWr = sm + SM_WRP;   float* sU  = sm + SM_USAGE;
            float* sP  = sm + SM_PREC;  float* sW2 = sm + SM_WW;
            float* sv  = scr + DS;
            float* ers  = sv + 480;
            float* scal = sv + 544;     // 0 wb,1 ag,2 wg,3 wkn,4-7 rb,8-11 free,
                                        // 12-15 rkn,16-27 modes,29 wcsum,30 wwsum
            float* u_s  = sv + 576;
            float* cwl  = sv + 704;     // exp(write logits)
            float* so   = sv + 832;     // scan buf / later n2
            float* su   = sv + 960;
            int*   irank= (int*)(sv + 1088);
            float* wwn  = sv + 1216;
            int*   rank4= (int*)(sv + 1344);   // 512; later crs
            float* crs  = sv + 1344;
            float* wtot = sv + 1856;    // 8
            float* fp_f = sv + 1920;    // 1024; fwv in low 512; later read partials
            float* fp_b = sv + 2944;    // 1024; bwv in low 512

            // 1. load interface
            if (tid < IFACE) sv[tid] = g_v[b*480 + tid];
            __syncthreads();

            // 2. parse (warp-parallel)
            if (wid < 4) {               // read key norms
                float x1 = sv[wid*64 + lane], x2 = sv[wid*64 + 32 + lane];
                float v = wredsum(x1*x1 + x2*x2);
                if (lane == 0) scal[12+wid] = sqrtf(v) + EPSF;
            } else if (wid == 4) {       // write key norm
                float x1 = sv[260 + lane], x2 = sv[260 + 32 + lane];
                float v = wredsum(x1*x1 + x2*x2);
                if (lane == 0) scal[3] = sqrtf(v) + EPSF;
            } else if (wid == 5) {
                if (lane < 4)       scal[4+lane] = 1.f + softplusf(sv[256+lane]);
                else if (lane < 8)  scal[8+lane-4] = sigm(sv[453+lane-4]);
                else if (lane == 8) scal[0] = 1.f + softplusf(sv[324]);
                else if (lane == 9) scal[1] = sigm(sv[457]);
                else if (lane == 10) scal[2] = sigm(sv[458]);
            } else if (wid == 6) {
                if (lane < 4) {
                    float m0=sv[459+3*lane], m1=sv[460+3*lane], m2=sv[461+3*lane];
                    float mx=fmaxf(m0,fmaxf(m1,m2));
                    float e0=expf(m0-mx), e1=expf(m1-mx), e2=expf(m2-mx);
                    float si=e0+e1+e2;
                    scal[16+3*lane]=e0/si; scal[17+3*lane]=e1/si; scal[18+3*lane]=e2/si;
                }
            } else if (wid == 7 || wid == 8) {
                int w = tid - 224;       // 0..63
                if (w < 64) ers[w] = sigm(sv[325+w]);
            }
            __syncthreads();

            // 3. usage + exp(write-content logit) on OLD M
            if (tid < 128) {
                float ret = 1.f;
                #pragma unroll
                for (int r=0;r<4;r++) ret *= (1.f - scal[8+r]*sWr[r*128+tid]);
                float uo = sU[tid], wwo = sW2[tid];
                float un = (uo + wwo - uo*wwo)*ret;
                u_s[tid] = un; sU[tid] = un;
                float d=0.f, n2=0.f;
                #pragma unroll 8
                for (int w=0;w<64;w++){ float m=sM[tid*65+w]; d+=m*sv[260+w]; n2+=m*m; }
                cwl[tid] = expf(scal[0]*d/((sqrtf(n2)+EPSF)*scal[3]));
            }
            __syncthreads();

            // 4. rank partials (512 thr) + write-softmax sum (warp 16)
            if (tid < 512) {
                int n = tid&127, q = tid>>7;
                float un = u_s[n]; int cnt = 0;
                #pragma unroll 8
                for (int m = q*32; m < q*32+32; m++) {
                    float um = u_s[m];
                    cnt += ((um<un) || (um==un && m<n)) ? 1 : 0;
                }
                rank4[q*128+n] = cnt;
            } else if (wid == 16) {
                float v = cwl[lane]+cwl[lane+32]+cwl[lane+64]+cwl[lane+96];
                v = wredsum(v);
                if (lane == 0) scal[29] = v;
            }
            __syncthreads();

            // 5. combine rank, scatter to sorted order
            if (tid < 128) {
                int rk = rank4[tid] + rank4[128+tid] + rank4[256+tid] + rank4[384+tid];
                irank[tid] = rk;
                float un = u_s[tid];
                so[rk] = un; su[rk] = un;
            }
            __syncthreads();

            // 6. cumprod scan: 4-warp shfl scan + warp totals
            if (wid < 4) {
                float v = so[wid*32 + lane];
                #pragma unroll
                for (int d = 1; d < 32; d <<= 1) {
                    float o = __shfl_up_sync(0xffffffffu, v, d);
                    if (lane >= d) v *= o;
                }
                so[wid*32 + lane] = v;
                if (lane == 31) wtot[wid] = v;
            }
            __syncthreads();

            // 7. allocation at own index + write weighting
            if (tid < 128) {
                int r = irank[tid];
                float excl = 1.f;
                if (r > 0) {
                    int rm = r-1;
                    float pf = so[rm];
                    int qw = rm >> 5;
                    for (int q2 = 0; q2 < qw; q2++) pf *= wtot[q2];
                    excl = pf;
                }
                float a = (1.f - u_s[tid]) * excl;
                float cwv = cwl[tid] / scal[29];
                float w = scal[2]*(scal[1]*a + (1.f-scal[1])*cwv);
                wwn[tid] = w; sW2[tid] = w;
            }
            __syncthreads();

            // 8. wwsum (warp 0) + M update + link update (all threads)
            if (wid == 0) {
                float v = wwn[lane]+wwn[lane+32]+wwn[lane+64]+wwn[lane+96];
                v = wredsum(v);
                if (lane == 0) scal[30] = v;
            }
            #pragma unroll
            for (int it = 0; it < 8; it++) {
                int idx = tid + it*NTHR;
                int n = idx>>6, w = idx&63;
                float m = sM[n*65+w];
                sM[n*65+w] = m*(1.f - wwn[n]*ers[w]) + wwn[n]*sv[389+w];
            }
            {
                int i = tid>>3, j0 = (tid&7)*16;
                float wwi = wwn[i];
                #pragma unroll
                for (int j = j0; j < j0+16; j++) {
                    float l = sL[i*129+j];
                    l = (1.f - wwi - wwn[j])*l + wwi*sP[j];
                    if (j == i) l = 0.f;
                    sL[i*129+j] = l;
                }
            }
            __syncthreads();

            // 9. precedence + fw/bw partials (all 1024, j split in 2)
            if (tid < 128) sP[tid] = (1.f - scal[30])*sP[tid] + wwn[tid];
            {
                int q = tid>>9, r = (tid>>7)&3, i = tid&127;
                float f = 0.f, bk = 0.f;
                #pragma unroll 8
                for (int j = q*64; j < q*64+64; j++) {
                    float wrj = sWr[r*128+j];
                    f  += sL[i*129+j]*wrj;
                    bk += sL[j*129+i]*wrj;
                }
                fp_f[q*512 + r*128 + i] = f;
                fp_b[q*512 + r*128 + i] = bk;
            }
            __syncthreads();

            // 10. combine fw/bw + read-content dots + row norms (new M)
            if (tid < 512) {
                fp_f[tid] += fp_f[512+tid];
                fp_b[tid] += fp_b[512+tid];
                int r = tid>>7, n = tid&127;
                float d = 0.f;
                #pragma unroll 8
                for (int w=0;w<64;w++) d += sM[n*65+w]*sv[r*64+w];
                crs[tid] = d;
            } else if (tid < 640) {
                int n = tid-512;
                float n2 = 0.f;
                #pragma unroll 8
                for (int w=0;w<64;w++){ float m=sM[n*65+w]; n2+=m*m; }
                so[n] = sqrtf(n2)+EPSF;
            }
            __syncthreads();

            // 11. exp(read logits)  (no max-subtract: |logit| <= beta, small)
            if (tid < 512) {
                int r = tid>>7, n = tid&127;
                crs[tid] = expf(scal[4+r]*crs[tid]/(so[n]*scal[12+r]));
            }
            __syncthreads();

            // 12. per-head sums (warps 0-3)
            if (wid < 4) {
                float v = crs[wid*128+lane]+crs[wid*128+32+lane]
                        + crs[wid*128+64+lane]+crs[wid*128+96+lane];
                v = wredsum(v);
                if (lane == 0) wtot[wid] = v;
            }
            __syncthreads();

            // 13. read weights -> sWr (new)
            if (tid < 512) {
                int r = tid>>7;
                float cc = crs[tid] / wtot[r];
                float w = scal[16+3*r]*fp_b[tid] + scal[17+3*r]*cc + scal[18+3*r]*fp_f[tid];
                sWr[tid] = w;
            }
            __syncthreads();

            // 14. reads partials (all 1024, n split in 4)
            {
                int q = tid>>8, rw = tid&255, r = rw>>6, w = rw&63;
                float s = 0.f;
                #pragma unroll 8
                for (int n = q*32; n < q*32+32; n++)
                    s += sWr[r*128+n]*sM[n*65+w];
                fp_f[q*256 + rw] = s;
            }
            __syncthreads();

            // 15. combine + store reads
            if (tid < 256) {
                float s = fp_f[tid] + fp_f[256+tid] + fp_f[512+tid] + fp_f[768+tid];
                g_reads[p^1][b*256 + tid] = s;
            }
        } else if (bq < 96) {
            if (t > 0)
                out_dev(Wout, bout, out, hprev, rdold, t-1, bq-32, scr);
        }
        // prestage x(t+1) into scr[0,16896) (all blocks; disjoint from D scratch)
        if (t+1 < TT) {
            int bb = wid;
            for (int kk = lane; kk < 512; kk += 32)
                scr[kk*33 + bb] = xseq[((size_t)bb*TT + t+1)*512 + kk];
        }
        gsync(bargen, barbase);
    }

    // final out(127): h(127) in g_h[0], reads(127) in g_reads[0]
    if (bq >= 32 && bq < 96)
        out_dev(Wout, bout, out, g_h[0], g_reads[0], 127, bq-32, scr);
}

extern "C" void kernel_launch(void* const* d_in, const int* in_sizes, int n_in,
                              void* d_out, int out_size)
{
    const float* xseq = (const float*)d_in[0];
    const float* Wx   = (const float*)d_in[1];
    const float* Wh   = (const float*)d_in[2];
    const float* bl   = (const float*)d_in[3];
    const float* Wif  = (const float*)d_in[4];
    const float* bif  = (const float*)d_in[5];
    const float* Wout = (const float*)d_in[6];
    const float* bout = (const float*)d_in[7];
    float* out = (float*)d_out;

    cudaFuncSetAttribute(dnc_kernel, cudaFuncAttributeMaxDynamicSharedMemorySize, SMEM_BYTES);
    dnc_kernel<<<NBLK, NTHR, SMEM_BYTES>>>(xseq, Wx, Wh, bl, Wif, bif, Wout, bout, out);
}

// round 14
// speedup vs baseline: 1.1891x; 1.1891x over previous
#include <cuda_runtime.h>
#include <math.h>

#define BB    32
#define TT    128
#define IFACE 471
#define EPSF  1e-6f
#define NBLK  128
#define NTHR  1024

// ---------------- smem layout (float offsets) ----------------
#define SM_M      0        // 128x65  persistent (blocks<32)
#define SM_L      8320     // 128x129 persistent
#define SM_WRP    24832    // 512 wr  persistent
#define SM_USAGE  25344    // 128
#define SM_PREC   25472    // 128
#define SM_WW     25600    // 128
#define SM_SCR    25728    // 21120 scratch
#define SCR_FLOATS 21120
#define SM_TOTAL  (SM_SCR + SCR_FLOATS)
#define SMEM_BYTES (SM_TOTAL*4)
#define DS        16896    // D-scratch offset inside scr (sT region is [0,16896))

// ---------------- device globals ----------------
__device__ float g_h[2][BB*512];
__device__ float g_reads[2][BB*256];
__device__ float g_v[BB*480];
__device__ unsigned g_count;   // monotonic barrier counter (never reset)

__device__ __forceinline__ float sigm(float x){ return 1.f/(1.f+expf(-x)); }
__device__ __forceinline__ float softplusf(float x){
    return (x>0.f) ? x+log1pf(expf(-x)) : log1pf(expf(x));
}
__device__ __forceinline__ float wredsum(float v){
    #pragma unroll
    for (int d=16; d; d>>=1) v += __shfl_xor_sync(0xffffffffu, v, d);
    return v;
}

// grid-wide barrier: generation counting, replay-safe (no reset), wrap-safe.
__device__ __forceinline__ void gsync() {
    __syncthreads();
    if (threadIdx.x == 0) {
        __threadfence();
        unsigned v = atomicAdd(&g_count, 1u);
        unsigned target = v - (v & (NBLK-1u)) + NBLK;   // end of this generation
        while ((int)(*(volatile unsigned*)&g_count - target) < 0) { }
        __threadfence();
    }
    __syncthreads();
}

#define FMA8() do { \
    acc[0]+=a0*w.x; acc[1]+=a0*w.y; acc[2]+=a0*w.z; acc[3]+=a0*w.w; \
    acc[4]+=a1*w.x; acc[5]+=a1*w.y; acc[6]+=a1*w.z; acc[7]+=a1*w.w; } while(0)

// ---------------- A1: x(tnext)@Wx[0:512] + h@Wh[0:512] into carried acc ------
__device__ __forceinline__ void a1_part(float* acc,
                                        const float* __restrict__ xseq,
                                        const float* __restrict__ Wx,
                                        const float* __restrict__ Wh,
                                        const float* __restrict__ hsrc,
                                        int tnext, int bq, float* scr)
{
    const int tid = threadIdx.x, wid = tid>>5, lane = tid&31;
    const int g = tid>>6, u = tid&63, bh = u&15, uc = u>>4;
    const int coff = uc*512 + bq*4;
    // stage x(tnext)^T: warp w owns batch w
    for (int kk = lane; kk < 512; kk += 32)
        scr[kk*33 + wid] = xseq[((size_t)wid*TT + tnext)*512 + kk];
    __syncthreads();
    {
        const int kb = g*32;
        const float* Wp = Wx + (size_t)kb*2048 + coff;
        #pragma unroll 8
        for (int kk = kb; kk < kb+32; kk++) {
            float4 w = *(const float4*)Wp; Wp += 2048;
            float a0 = scr[kk*33 + bh], a1 = scr[kk*33 + bh + 16];
            FMA8();
        }
    }
    __syncthreads();
    // stage h^T
    for (int kk = lane; kk < 512; kk += 32)
        scr[kk*33 + wid] = hsrc[wid*512 + kk];
    __syncthreads();
    {
        const int kb = g*32;
        const float* Wp = Wh + (size_t)kb*2048 + coff;
        #pragma unroll 8
        for (int kk = kb; kk < kb+32; kk++) {
            float4 w = *(const float4*)Wp; Wp += 2048;
            float a0 = scr[kk*33 + bh], a1 = scr[kk*33 + bh + 16];
            FMA8();
        }
    }
    __syncthreads();
}

// ---------------- out GEMM: 64 blocks (obq 0..63), 8 cols each ----------------
__device__ __forceinline__ void out_dev(const float* __restrict__ Wout,
                                        const float* __restrict__ bout,
                                        float* __restrict__ out,
                                        const float* __restrict__ hsrc,
                                        const float* __restrict__ rsrc,
                                        int tout, int obq, float* scr)
{
    const int tid = threadIdx.x;
    const int wid = tid>>5, lane = tid&31;
    const int g = tid>>7, u = tid&127, b = u&31, uc = u>>5;
    float a0 = 0.f, a1 = 0.f;
    for (int hh = 0; hh < 2; hh++) {
        {   // stage [reads,h] transposed: warp w owns batch w (segmented)
            int bb = wid;
            if (hh == 0) {
                for (int kk = lane; kk < 256; kk += 32)
                    scr[kk*33 + bb] = rsrc[bb*256 + kk];
                for (int kk = 256+lane; kk < 384; kk += 32)
                    scr[kk*33 + bb] = hsrc[bb*512 + (kk-256)];
            } else {
                for (int kk = lane; kk < 384; kk += 32)
                    scr[kk*33 + bb] = hsrc[bb*512 + 128 + kk];
            }
        }
        __syncthreads();
        int kb = g*48;
        const float* Wp = Wout + (size_t)(hh*384 + kb)*512 + obq*8 + uc*2;
        #pragma unroll 8
        for (int kk = 0; kk < 48; kk++) {
            float a = scr[(kb+kk)*33 + b];
            float2 w = *(const float2*)Wp; Wp += 512;
            a0 += a*w.x; a1 += a*w.y;
        }
        __syncthreads();
    }
    float* zbo = scr + 12672;
    zbo[g*256 + (uc*2  )*32 + b] = a0;
    zbo[g*256 + (uc*2+1)*32 + b] = a1;
    __syncthreads();
    if (tid < 256) {
        int b2 = tid&31, co = tid>>5;
        int col = obq*8 + co;
        float o = bout[col];
        #pragma unroll
        for (int gg = 0; gg < 8; gg++) o += zbo[gg*256 + co*32 + b2];
        out[((size_t)b2*TT + tout)*512 + col] = o;
    }
    __syncthreads();
}

// ---------------- persistent DNC kernel ----------------
__global__ void __launch_bounds__(NTHR, 1)
dnc_kernel(const float* __restrict__ xseq, const float* __restrict__ Wx,
           const float* __restrict__ Wh,   const float* __restrict__ bl,
           const float* __restrict__ Wif,  const float* __restrict__ bif,
           const float* __restrict__ Wout, const float* __restrict__ bout,
           float* __restrict__ out)
{
    extern __shared__ float sm[];
    const int tid = threadIdx.x;
    const int bq  = blockIdx.x;
    const int wid = tid>>5, lane = tid&31;
    float* scr = sm + SM_SCR;

    // ---------- init ----------
    for (int i = bq*NTHR + tid; i < BB*512; i += NBLK*NTHR) g_h[0][i] = 0.f;
    for (int i = bq*NTHR + tid; i < BB*256; i += NBLK*NTHR) g_reads[0][i] = 0.f;
    if (bq < 32)
        for (int i = tid; i < SM_SCR; i += NTHR) sm[i] = 0.f;
    float c_reg = 0.f;   // c for (b=tid&31, j=bq*4+(tid>>5)) when tid<128
    float acc[8] = {0,0,0,0,0,0,0,0};   // carried LSTM partials
    gsync();

    // A1 for step 0 (h = 0, reads handled in slot 1)
    a1_part(acc, xseq, Wx, Wh, g_h[0], 0, bq, scr);

    for (int t = 0; t < TT; t++) {
        const int p = t & 1;
        const float* hprev = g_h[p];
        float* hnew = g_h[p^1];
        const float* rdold = g_reads[p];

        // ========== slot 1: A2 (reads @ Wx[512:768]) + gates + h ==========
        {
            const int g = tid>>6, u = tid&63, bh = u&15, uc = u>>4;
            const int coff = uc*512 + bq*4;
            // stage reads^T: 256 rows
            for (int kk = lane; kk < 256; kk += 32)
                scr[kk*33 + wid] = rdold[wid*256 + kk];
            __syncthreads();
            {
                const int kb = g*16;
                const float* Wp = Wx + (size_t)(512 + kb)*2048 + coff;
                #pragma unroll 8
                for (int kk = kb; kk < kb+16; kk++) {
                    float4 w = *(const float4*)Wp; Wp += 2048;
                    float a0 = scr[kk*33 + bh], a1 = scr[kk*33 + bh + 16];
                    FMA8();
                }
            }
            __syncthreads();
            float* zb = scr;           // 16 x 512 partials (sT dead)
            #pragma unroll
            for (int ci = 0; ci < 4; ci++) {
                zb[g*512 + (uc*4+ci)*32 + bh     ] = acc[ci];
                zb[g*512 + (uc*4+ci)*32 + bh + 16] = acc[4+ci];
            }
            #pragma unroll
            for (int i = 0; i < 8; i++) acc[i] = 0.f;   // reset for next A1
            __syncthreads();
            float* zsum = scr + 8192;
            if (tid < 512) {
                float s = 0.f;
                #pragma unroll
                for (int gg = 0; gg < 16; gg++) s += zb[gg*512 + tid];
                zsum[tid] = s;
            }
            __syncthreads();
            if (tid < 128) {
                int b = tid & 31, jj = tid >> 5;
                int j = bq*4 + jj;
                float zi = bl[       j] + zsum[(0*4+jj)*32 + b];
                float zf = bl[512  + j] + zsum[(1*4+jj)*32 + b];
                float zg = bl[1024 + j] + zsum[(2*4+jj)*32 + b];
                float zo = bl[1536 + j] + zsum[(3*4+jj)*32 + b];
                float ig = sigm(zi), fg = sigm(zf);
                float gg = tanhf(zg), og = sigm(zo);
                c_reg = fg*c_reg + ig*gg;
                hnew[b*512 + j] = og * tanhf(c_reg);
            }
        }
        gsync();

        // ========== slot 2: D-blocks A1(t+1) || others iface C ==========
        if (bq < 32) {
            if (t+1 < TT)
                a1_part(acc, xseq, Wx, Wh, hnew, t+1, bq, scr);
        } else {
            const int aq = bq - 32;
            const int col0 = aq*5;                 // cols col0..col0+4 (<471)
            // stage h^T
            for (int kk = lane; kk < 512; kk += 32)
                scr[kk*33 + wid] = hnew[wid*512 + kk];
            __syncthreads();
            float a5[5] = {0,0,0,0,0};
            {
                const float* Wp = Wif + (size_t)(wid*16)*IFACE + col0;
                #pragma unroll 4
                for (int kk = wid*16; kk < wid*16+16; kk++) {
                    float a = scr[kk*33 + lane];
                    #pragma unroll
                    for (int ci = 0; ci < 5; ci++) {
                        float w = (col0+ci < IFACE) ? Wp[ci] : 0.f;
                        a5[ci] += a*w;
                    }
                    Wp += IFACE;
                }
            }
            __syncthreads();
            float* zbi = scr;          // 32 x 5 x 32 (sT dead)
            #pragma unroll
            for (int ci = 0; ci < 5; ci++)
                zbi[(wid*5+ci)*32 + lane] = a5[ci];
            __syncthreads();
            if (tid < 160) {
                int ci = tid>>5, b2 = tid&31;
                float v = 0.f;
                #pragma unroll 8
                for (int w2 = 0; w2 < 32; w2++) v += zbi[(w2*5+ci)*32 + b2];
                int c2 = col0 + ci;
                if (c2 < IFACE) g_v[b2*480 + c2] = v + bif[c2];
            }
            __syncthreads();
        }
        gsync();

        // ==== slot 3: D (0-31) || out(t-1)+A1 (32-95) || A1 (96-127) ======
        if (bq < 32) {
            const int b = bq;
            float* sM  = sm + SM_M;     float* sL  = sm + SM_L;
            float* sWr = sm + SM_WRP;   float* sU  = sm + SM_USAGE;
            float* sP  = sm + SM_PREC;  float* sW2 = sm + SM_WW;
            float* sv  = scr + DS;
            float* ers  = sv + 480;
            float* scal = sv + 544;
            float* u_s  = sv + 576;
            float* cwl  = sv + 704;
            float* so   = sv + 832;
            float* su   = sv + 960;
            int*   irank= (int*)(sv + 1088);
            float* wwn  = sv + 1216;
            int*   rank4= (int*)(sv + 1344);
            float* crs  = sv + 1344;
            float* wtot = sv + 1856;
            float* fp_f = sv + 1920;
            float* fp_b = sv + 2944;

            if (tid < IFACE) sv[tid] = g_v[b*480 + tid];
            __syncthreads();

            if (wid < 4) {
                float x1 = sv[wid*64 + lane], x2 = sv[wid*64 + 32 + lane];
                float v = wredsum(x1*x1 + x2*x2);
                if (lane == 0) scal[12+wid] = sqrtf(v) + EPSF;
            } else if (wid == 4) {
                float x1 = sv[260 + lane], x2 = sv[260 + 32 + lane];
                float v = wredsum(x1*x1 + x2*x2);
                if (lane == 0) scal[3] = sqrtf(v) + EPSF;
            } else if (wid == 5) {
                if (lane < 4)       scal[4+lane] = 1.f + softplusf(sv[256+lane]);
                else if (lane < 8)  scal[8+lane-4] = sigm(sv[453+lane-4]);
                else if (lane == 8) scal[0] = 1.f + softplusf(sv[324]);
                else if (lane == 9) scal[1] = sigm(sv[457]);
                else if (lane == 10) scal[2] = sigm(sv[458]);
            } else if (wid == 6) {
                if (lane < 4) {
                    float m0=sv[459+3*lane], m1=sv[460+3*lane], m2=sv[461+3*lane];
                    float mx=fmaxf(m0,fmaxf(m1,m2));
                    float e0=expf(m0-mx), e1=expf(m1-mx), e2=expf(m2-mx);
                    float si=e0+e1+e2;
                    scal[16+3*lane]=e0/si; scal[17+3*lane]=e1/si; scal[18+3*lane]=e2/si;
                }
            } else if (wid == 7 || wid == 8) {
                int w = tid - 224;
                if (w < 64) ers[w] = sigm(sv[325+w]);
            }
            __syncthreads();

            if (tid < 128) {
                float ret = 1.f;
                #pragma unroll
                for (int r=0;r<4;r++) ret *= (1.f - scal[8+r]*sWr[r*128+tid]);
                float uo = sU[tid], wwo = sW2[tid];
                float un = (uo + wwo - uo*wwo)*ret;
                u_s[tid] = un; sU[tid] = un;
                float d=0.f, n2=0.f;
                #pragma unroll 8
                for (int w=0;w<64;w++){ float m=sM[tid*65+w]; d+=m*sv[260+w]; n2+=m*m; }
                cwl[tid] = expf(scal[0]*d/((sqrtf(n2)+EPSF)*scal[3]));
            }
            __syncthreads();

            if (tid < 512) {
                int n = tid&127, q = tid>>7;
                float un = u_s[n]; int cnt = 0;
                #pragma unroll 8
                for (int m = q*32; m < q*32+32; m++) {
                    float um = u_s[m];
                    cnt += ((um<un) || (um==un && m<n)) ? 1 : 0;
                }
                rank4[q*128+n] = cnt;
            } else if (wid == 16) {
                float v = cwl[lane]+cwl[lane+32]+cwl[lane+64]+cwl[lane+96];
                v = wredsum(v);
                if (lane == 0) scal[29] = v;
            }
            __syncthreads();

            if (tid < 128) {
                int rk = rank4[tid] + rank4[128+tid] + rank4[256+tid] + rank4[384+tid];
                irank[tid] = rk;
                float un = u_s[tid];
                so[rk] = un; su[rk] = un;
            }
            __syncthreads();

            if (wid < 4) {
                float v = so[wid*32 + lane];
                #pragma unroll
                for (int d = 1; d < 32; d <<= 1) {
                    float o = __shfl_up_sync(0xffffffffu, v, d);
                    if (lane >= d) v *= o;
                }
                so[wid*32 + lane] = v;
                if (lane == 31) wtot[wid] = v;
            }
            __syncthreads();

            if (tid < 128) {
                int r = irank[tid];
                float excl = 1.f;
                if (r > 0) {
                    int rm = r-1;
                    float pf = so[rm];
                    int qw = rm >> 5;
                    for (int q2 = 0; q2 < qw; q2++) pf *= wtot[q2];
                    excl = pf;
                }
                float a = (1.f - u_s[tid]) * excl;
                float cwv = cwl[tid] / scal[29];
                float w = scal[2]*(scal[1]*a + (1.f-scal[1])*cwv);
                wwn[tid] = w; sW2[tid] = w;
            }
            __syncthreads();

            if (wid == 0) {
                float v = wwn[lane]+wwn[lane+32]+wwn[lane+64]+wwn[lane+96];
                v = wredsum(v);
                if (lane == 0) scal[30] = v;
            }
            #pragma unroll
            for (int it = 0; it < 8; it++) {
                int idx = tid + it*NTHR;
                int n = idx>>6, w = idx&63;
                float m = sM[n*65+w];
                sM[n*65+w] = m*(1.f - wwn[n]*ers[w]) + wwn[n]*sv[389+w];
            }
            {
                int i = tid>>3, j0 = (tid&7)*16;
                float wwi = wwn[i];
                #pragma unroll
                for (int j = j0; j < j0+16; j++) {
                    float l = sL[i*129+j];
                    l = (1.f - wwi - wwn[j])*l + wwi*sP[j];
                    if (j == i) l = 0.f;
                    sL[i*129+j] = l;
                }
            }
            __syncthreads();

            if (tid < 128) sP[tid] = (1.f - scal[30])*sP[tid] + wwn[tid];
            {
                int q = tid>>9, r = (tid>>7)&3, i = tid&127;
                float f = 0.f, bk = 0.f;
                #pragma unroll 8
                for (int j = q*64; j < q*64+64; j++) {
                    float wrj = sWr[r*128+j];
                    f  += sL[i*129+j]*wrj;
                    bk += sL[j*129+i]*wrj;
                }
                fp_f[q*512 + r*128 + i] = f;
                fp_b[q*512 + r*128 + i] = bk;
            }
            __syncthreads();

            if (tid < 512) {
                fp_f[tid] += fp_f[512+tid];
                fp_b[tid] += fp_b[512+tid];
                int r = tid>>7, n = tid&127;
                float d = 0.f;
                #pragma unroll 8
                for (int w=0;w<64;w++) d += sM[n*65+w]*sv[r*64+w];
                crs[tid] = d;
            } else if (tid < 640) {
                int n = tid-512;
                float n2 = 0.f;
                #pragma unroll 8
                for (int w=0;w<64;w++){ float m=sM[n*65+w]; n2+=m*m; }
                so[n] = sqrtf(n2)+EPSF;
            }
            __syncthreads();

            if (tid < 512) {
                int r = tid>>7, n = tid&127;
                crs[tid] = expf(scal[4+r]*crs[tid]/(so[n]*scal[12+r]));
            }
            __syncthreads();

            if (wid < 4) {
                float v = crs[wid*128+lane]+crs[wid*128+32+lane]
                        + crs[wid*128+64+lane]+crs[wid*128+96+lane];
                v = wredsum(v);
                if (lane == 0) wtot[wid] = v;
            }
            __syncthreads();

            if (tid < 512) {
                int r = tid>>7;
                float cc = crs[tid] / wtot[r];
                float w = scal[16+3*r]*fp_b[tid] + scal[17+3*r]*cc + scal[18+3*r]*fp_f[tid];
                sWr[tid] = w;
            }
            __syncthreads();

            {
                int q = tid>>8, rw = tid&255, r = rw>>6, w = rw&63;
                float s = 0.f;
                #pragma unroll 8
                for (int n = q*32; n < q*32+32; n++)
                    s += sWr[r*128+n]*sM[n*65+w];
                fp_f[q*256 + rw] = s;
            }
            __syncthreads();

            if (tid < 256) {
                float s = fp_f[tid] + fp_f[256+tid] + fp_f[512+tid] + fp_f[768+tid];
                g_reads[p^1][b*256 + tid] = s;
            }
        } else if (bq < 96) {
            if (t > 0)
                out_dev(Wout, bout, out, hprev, rdold, t-1, bq-32, scr);
            if (t+1 < TT)
                a1_part(acc, xseq, Wx, Wh, hnew, t+1, bq, scr);
        } else {
            if (t+1 < TT)
                a1_part(acc, xseq, Wx, Wh, hnew, t+1, bq, scr);
        }
        gsync();
    }

    // final out(127): h(127) in g_h[0], reads(127) in g_reads[0]
    if (bq >= 32 && bq < 96)
        out_dev(Wout, bout, out, g_h[0], g_reads[0], 127, bq-32, scr);
}

extern "C" void kernel_launch(void* const* d_in, const int* in_sizes, int n_in,
                              void* d_out, int out_size)
{
    const float* xseq = (const float*)d_in[0];
    const float* Wx   = (const float*)d_in[1];
    const float* Wh   = (const float*)d_in[2];
    const float* bl   = (const float*)d_in[3];
    const float* Wif  = (const float*)d_in[4];
    const float* bif  = (const float*)d_in[5];
    const float* Wout = (const float*)d_in[6];
    const float* bout = (const float*)d_in[7];
    float* out = (float*)d_out;

    cudaFuncSetAttribute(dnc_kernel, cudaFuncAttributeMaxDynamicSharedMemorySize, SMEM_BYTES);
    dnc_kernel<<<NBLK, NTHR, SMEM_BYTES>>>(xseq, Wx, Wh, bl, Wif, bif, Wout, bout, out);
}

// round 15
// speedup vs baseline: 1.3098x; 1.1015x over previous
#include <cuda_runtime.h>
#include <math.h>

#define BB    32
#define TT    128
#define IFACE 471
#define EPSF  1e-6f
#define NBLK  128
#define NTHR  1024

// ---------------- smem layout (float offsets) ----------------
#define SM_M      0        // 128x65  persistent (blocks<32)
#define SM_L      8320     // 128x129 persistent
#define SM_WRP    24832    // 512 wr  persistent
#define SM_USAGE  25344    // 128
#define SM_PREC   25472    // 128
#define SM_WW     25600    // 128
#define SM_SCR    25728    // 21120 scratch
#define SCR_FLOATS 21120
#define SM_TOTAL  (SM_SCR + SCR_FLOATS)
#define SMEM_BYTES (SM_TOTAL*4)
#define DS        16896    // D-scratch offset inside scr (sT region is [0,16896))

// ---------------- device globals ----------------
__device__ float g_h[2][BB*512];
__device__ float g_reads[2][BB*256];
__device__ float g_v[BB*480];
__device__ unsigned g_count;     // init full-barrier counter (monotonic)
__device__ unsigned g_bars[4];   // 0: h(128/step) 1: v(96/step) 2: r(32/step)

__device__ __forceinline__ float sigm(float x){ return 1.f/(1.f+expf(-x)); }
__device__ __forceinline__ float softplusf(float x){
    return (x>0.f) ? x+log1pf(expf(-x)) : log1pf(expf(x));
}
__device__ __forceinline__ float wredsum(float v){
    #pragma unroll
    for (int d=16; d; d>>=1) v += __shfl_xor_sync(0xffffffffu, v, d);
    return v;
}

// full grid barrier (init only)
__device__ __forceinline__ void gsync_full() {
    __syncthreads();
    if (threadIdx.x == 0) {
        __threadfence();
        unsigned v = atomicAdd(&g_count, 1u);
        unsigned target = v - (v & (NBLK-1u)) + NBLK;
        while ((int)(*(volatile unsigned*)&g_count - target) < 0) { }
        __threadfence();
    }
    __syncthreads();
}

__device__ __forceinline__ void bar_arrive(int i){
    __threadfence();
    atomicAdd(&g_bars[i], 1u);
}
__device__ __forceinline__ void bar_spin(int i, unsigned target){
    while ((int)(*(volatile unsigned*)&g_bars[i] - target) < 0) { }
    __threadfence();
}

#define FMA8() do { \
    acc[0]+=a0*w.x; acc[1]+=a0*w.y; acc[2]+=a0*w.z; acc[3]+=a0*w.w; \
    acc[4]+=a1*w.x; acc[5]+=a1*w.y; acc[6]+=a1*w.z; acc[7]+=a1*w.w; } while(0)

// ---------------- A1: x(tnext)@Wx[0:512] + h@Wh[0:512] into carried acc ------
__device__ __forceinline__ void a1_part(float* acc,
                                        const float* __restrict__ xseq,
                                        const float* __restrict__ Wx,
                                        const float* __restrict__ Wh,
                                        const float* __restrict__ hsrc,
                                        int tnext, int bq, float* scr)
{
    const int tid = threadIdx.x, wid = tid>>5, lane = tid&31;
    const int g = tid>>6, u = tid&63, bh = u&15, uc = u>>4;
    const int coff = uc*512 + bq*4;
    // stage x(tnext)^T: warp w owns batch w
    for (int kk = lane; kk < 512; kk += 32)
        scr[kk*33 + wid] = xseq[((size_t)wid*TT + tnext)*512 + kk];
    __syncthreads();
    {
        const int kb = g*32;
        const float* Wp = Wx + (size_t)kb*2048 + coff;
        #pragma unroll 8
        for (int kk = kb; kk < kb+32; kk++) {
            float4 w = *(const float4*)Wp; Wp += 2048;
            float a0 = scr[kk*33 + bh], a1 = scr[kk*33 + bh + 16];
            FMA8();
        }
    }
    __syncthreads();
    // stage h^T
    for (int kk = lane; kk < 512; kk += 32)
        scr[kk*33 + wid] = hsrc[wid*512 + kk];
    __syncthreads();
    {
        const int kb = g*32;
        const float* Wp = Wh + (size_t)kb*2048 + coff;
        #pragma unroll 8
        for (int kk = kb; kk < kb+32; kk++) {
            float4 w = *(const float4*)Wp; Wp += 2048;
            float a0 = scr[kk*33 + bh], a1 = scr[kk*33 + bh + 16];
            FMA8();
        }
    }
    __syncthreads();
}

// ---------------- out GEMM: 64 blocks (obq 0..63), 8 cols each ----------------
__device__ __forceinline__ void out_dev(const float* __restrict__ Wout,
                                        const float* __restrict__ bout,
                                        float* __restrict__ out,
                                        const float* __restrict__ hsrc,
                                        const float* __restrict__ rsrc,
                                        int tout, int obq, float* scr)
{
    const int tid = threadIdx.x;
    const int wid = tid>>5, lane = tid&31;
    const int g = tid>>7, u = tid&127, b = u&31, uc = u>>5;
    float a0 = 0.f, a1 = 0.f;
    for (int hh = 0; hh < 2; hh++) {
        {   // stage [reads,h] transposed: warp w owns batch w (segmented)
            int bb = wid;
            if (hh == 0) {
                for (int kk = lane; kk < 256; kk += 32)
                    scr[kk*33 + bb] = rsrc[bb*256 + kk];
                for (int kk = 256+lane; kk < 384; kk += 32)
                    scr[kk*33 + bb] = hsrc[bb*512 + (kk-256)];
            } else {
                for (int kk = lane; kk < 384; kk += 32)
                    scr[kk*33 + bb] = hsrc[bb*512 + 128 + kk];
            }
        }
        __syncthreads();
        int kb = g*48;
        const float* Wp = Wout + (size_t)(hh*384 + kb)*512 + obq*8 + uc*2;
        #pragma unroll 8
        for (int kk = 0; kk < 48; kk++) {
            float a = scr[(kb+kk)*33 + b];
            float2 w = *(const float2*)Wp; Wp += 512;
            a0 += a*w.x; a1 += a*w.y;
        }
        __syncthreads();
    }
    float* zbo = scr + 12672;
    zbo[g*256 + (uc*2  )*32 + b] = a0;
    zbo[g*256 + (uc*2+1)*32 + b] = a1;
    __syncthreads();
    if (tid < 256) {
        int b2 = tid&31, co = tid>>5;
        int col = obq*8 + co;
        float o = bout[col];
        #pragma unroll
        for (int gg = 0; gg < 8; gg++) o += zbo[gg*256 + co*32 + b2];
        out[((size_t)b2*TT + tout)*512 + col] = o;
    }
    __syncthreads();
}

// ---------------- persistent DNC kernel ----------------
__global__ void __launch_bounds__(NTHR, 1)
dnc_kernel(const float* __restrict__ xseq, const float* __restrict__ Wx,
           const float* __restrict__ Wh,   const float* __restrict__ bl,
           const float* __restrict__ Wif,  const float* __restrict__ bif,
           const float* __restrict__ Wout, const float* __restrict__ bout,
           float* __restrict__ out)
{
    extern __shared__ float sm[];
    __shared__ unsigned sbase[4];
    const int tid = threadIdx.x;
    const int bq  = blockIdx.x;
    const int wid = tid>>5, lane = tid&31;
    float* scr = sm + SM_SCR;

    // snapshot barrier bases BEFORE init barrier (no arrivals can precede it)
    if (tid == 0) {
        sbase[0] = *(volatile unsigned*)&g_bars[0];
        sbase[1] = *(volatile unsigned*)&g_bars[1];
        sbase[2] = *(volatile unsigned*)&g_bars[2];
    }

    // ---------- init ----------
    for (int i = bq*NTHR + tid; i < BB*512; i += NBLK*NTHR) g_h[0][i] = 0.f;
    for (int i = bq*NTHR + tid; i < BB*256; i += NBLK*NTHR) g_reads[0][i] = 0.f;
    if (bq < 32)
        for (int i = tid; i < SM_SCR; i += NTHR) sm[i] = 0.f;
    float c_reg = 0.f;   // c for (b=tid&31, j=bq*4+(tid>>5)) when tid<128
    float acc[8] = {0,0,0,0,0,0,0,0};   // carried LSTM partials
    gsync_full();

    // A1 for step 0 (h = 0, reads handled in slot 1)
    a1_part(acc, xseq, Wx, Wh, g_h[0], 0, bq, scr);

    for (int t = 0; t < TT; t++) {
        const int p = t & 1;
        const float* hprev = g_h[p];
        float* hnew = g_h[p^1];
        const float* rdold = g_reads[p];
        const unsigned step1 = (unsigned)(t+1);

        // ========== slot 1: A2 (reads @ Wx[512:768]) + gates + h ==========
        {
            const int g = tid>>6, u = tid&63, bh = u&15, uc = u>>4;
            const int coff = uc*512 + bq*4;
            // stage reads^T: 256 rows
            for (int kk = lane; kk < 256; kk += 32)
                scr[kk*33 + wid] = rdold[wid*256 + kk];
            __syncthreads();
            {
                const int kb = g*16;
                const float* Wp = Wx + (size_t)(512 + kb)*2048 + coff;
                #pragma unroll 8
                for (int kk = kb; kk < kb+16; kk++) {
                    float4 w = *(const float4*)Wp; Wp += 2048;
                    float a0 = scr[kk*33 + bh], a1 = scr[kk*33 + bh + 16];
                    FMA8();
                }
            }
            __syncthreads();
            float* zb = scr;           // 16 x 512 partials (sT dead)
            #pragma unroll
            for (int ci = 0; ci < 4; ci++) {
                zb[g*512 + (uc*4+ci)*32 + bh     ] = acc[ci];
                zb[g*512 + (uc*4+ci)*32 + bh + 16] = acc[4+ci];
            }
            #pragma unroll
            for (int i = 0; i < 8; i++) acc[i] = 0.f;   // reset for next A1
            __syncthreads();
            float* zsum = scr + 8192;
            if (tid < 512) {
                float s = 0.f;
                #pragma unroll
                for (int gg = 0; gg < 16; gg++) s += zb[gg*512 + tid];
                zsum[tid] = s;
            }
            __syncthreads();
            if (tid < 128) {
                int b = tid & 31, jj = tid >> 5;
                int j = bq*4 + jj;
                float zi = bl[       j] + zsum[(0*4+jj)*32 + b];
                float zf = bl[512  + j] + zsum[(1*4+jj)*32 + b];
                float zg = bl[1024 + j] + zsum[(2*4+jj)*32 + b];
                float zo = bl[1536 + j] + zsum[(3*4+jj)*32 + b];
                float ig = sigm(zi), fg = sigm(zf);
                float gg = tanhf(zg), og = sigm(zo);
                c_reg = fg*c_reg + ig*gg;
                hnew[b*512 + j] = og * tanhf(c_reg);
            }
        }
        // ---- bar_h: full (all arrive, all wait) ----
        __syncthreads();
        if (tid == 0) { bar_arrive(0); bar_spin(0, sbase[0] + step1*128u); }
        __syncthreads();

        // ========== slot 2: D-blocks A1(t+1) || others iface C ==========
        if (bq < 32) {
            if (t+1 < TT)
                a1_part(acc, xseq, Wx, Wh, hnew, t+1, bq, scr);
            // ---- bar_v: D-blocks WAIT for the 96 C producers ----
            __syncthreads();
            if (tid == 0) bar_spin(1, sbase[1] + step1*96u);
            __syncthreads();
        } else {
            const int aq = bq - 32;
            const int col0 = aq*5;                 // cols col0..col0+4 (<471)
            // stage h^T
            for (int kk = lane; kk < 512; kk += 32)
                scr[kk*33 + wid] = hnew[wid*512 + kk];
            __syncthreads();
            float a5[5] = {0,0,0,0,0};
            {
                const float* Wp = Wif + (size_t)(wid*16)*IFACE + col0;
                #pragma unroll 4
                for (int kk = wid*16; kk < wid*16+16; kk++) {
                    float a = scr[kk*33 + lane];
                    #pragma unroll
                    for (int ci = 0; ci < 5; ci++) {
                        float w = (col0+ci < IFACE) ? Wp[ci] : 0.f;
                        a5[ci] += a*w;
                    }
                    Wp += IFACE;
                }
            }
            __syncthreads();
            float* zbi = scr;          // 32 x 5 x 32 (sT dead)
            #pragma unroll
            for (int ci = 0; ci < 5; ci++)
                zbi[(wid*5+ci)*32 + lane] = a5[ci];
            __syncthreads();
            if (tid < 160) {
                int ci = tid>>5, b2 = tid&31;
                float v = 0.f;
                #pragma unroll 8
                for (int w2 = 0; w2 < 32; w2++) v += zbi[(w2*5+ci)*32 + b2];
                int c2 = col0 + ci;
                if (c2 < IFACE) g_v[b2*480 + c2] = v + bif[c2];
            }
            // ---- bar_v: producers ARRIVE, do not wait ----
            __syncthreads();
            if (tid == 0) bar_arrive(1);
        }

        // ==== slot 3: D (0-31) || out(t-1)+A1 (32-95) || A1 (96-127) ======
        if (bq < 32) {
            const int b = bq;
            float* sM  = sm + SM_M;     float* sL  = sm + SM_L;
            float* sWr = sm + SM_WRP;   float* sU  = sm + SM_USAGE;
            float* sP  = sm + SM_PREC;  float* sW2 = sm + SM_WW;
            float* sv  = scr + DS;
            float* ers  = sv + 480;
            float* scal = sv + 544;
            float* u_s  = sv + 576;
            float* cwl  = sv + 704;
            float* so   = sv + 832;
            float* su   = sv + 960;
            int*   irank= (int*)(sv + 1088);
            float* wwn  = sv + 1216;
            int*   rank4= (int*)(sv + 1344);
            float* crs  = sv + 1344;
            float* wtot = sv + 1856;
            float* fp_f = sv + 1920;
            float* fp_b = sv + 2944;

            if (tid < IFACE) sv[tid] = g_v[b*480 + tid];
            __syncthreads();

            if (wid < 4) {
                float x1 = sv[wid*64 + lane], x2 = sv[wid*64 + 32 + lane];
                float v = wredsum(x1*x1 + x2*x2);
                if (lane == 0) scal[12+wid] = sqrtf(v) + EPSF;
            } else if (wid == 4) {
                float x1 = sv[260 + lane], x2 = sv[260 + 32 + lane];
                float v = wredsum(x1*x1 + x2*x2);
                if (lane == 0) scal[3] = sqrtf(v) + EPSF;
            } else if (wid == 5) {
                if (lane < 4)       scal[4+lane] = 1.f + softplusf(sv[256+lane]);
                else if (lane < 8)  scal[8+lane-4] = sigm(sv[453+lane-4]);
                else if (lane == 8) scal[0] = 1.f + softplusf(sv[324]);
                else if (lane == 9) scal[1] = sigm(sv[457]);
                else if (lane == 10) scal[2] = sigm(sv[458]);
            } else if (wid == 6) {
                if (lane < 4) {
                    float m0=sv[459+3*lane], m1=sv[460+3*lane], m2=sv[461+3*lane];
                    float mx=fmaxf(m0,fmaxf(m1,m2));
                    float e0=expf(m0-mx), e1=expf(m1-mx), e2=expf(m2-mx);
                    float si=e0+e1+e2;
                    scal[16+3*lane]=e0/si; scal[17+3*lane]=e1/si; scal[18+3*lane]=e2/si;
                }
            } else if (wid == 7 || wid == 8) {
                int w = tid - 224;
                if (w < 64) ers[w] = sigm(sv[325+w]);
            }
            __syncthreads();

            if (tid < 128) {
                float ret = 1.f;
                #pragma unroll
                for (int r=0;r<4;r++) ret *= (1.f - scal[8+r]*sWr[r*128+tid]);
                float uo = sU[tid], wwo = sW2[tid];
                float un = (uo + wwo - uo*wwo)*ret;
                u_s[tid] = un; sU[tid] = un;
                float d=0.f, n2=0.f;
                #pragma unroll 8
                for (int w=0;w<64;w++){ float m=sM[tid*65+w]; d+=m*sv[260+w]; n2+=m*m; }
                cwl[tid] = expf(scal[0]*d/((sqrtf(n2)+EPSF)*scal[3]));
            }
            __syncthreads();

            if (tid < 512) {
                int n = tid&127, q = tid>>7;
                float un = u_s[n]; int cnt = 0;
                #pragma unroll 8
                for (int m = q*32; m < q*32+32; m++) {
                    float um = u_s[m];
                    cnt += ((um<un) || (um==un && m<n)) ? 1 : 0;
                }
                rank4[q*128+n] = cnt;
            } else if (wid == 16) {
                float v = cwl[lane]+cwl[lane+32]+cwl[lane+64]+cwl[lane+96];
                v = wredsum(v);
                if (lane == 0) scal[29] = v;
            }
            __syncthreads();

            if (tid < 128) {
                int rk = rank4[tid] + rank4[128+tid] + rank4[256+tid] + rank4[384+tid];
                irank[tid] = rk;
                float un = u_s[tid];
                so[rk] = un; su[rk] = un;
            }
            __syncthreads();

            if (wid < 4) {
                float v = so[wid*32 + lane];
                #pragma unroll
                for (int d = 1; d < 32; d <<= 1) {
                    float o = __shfl_up_sync(0xffffffffu, v, d);
                    if (lane >= d) v *= o;
                }
                so[wid*32 + lane] = v;
                if (lane == 31) wtot[wid] = v;
            }
            __syncthreads();

            if (tid < 128) {
                int r = irank[tid];
                float excl = 1.f;
                if (r > 0) {
                    int rm = r-1;
                    float pf = so[rm];
                    int qw = rm >> 5;
                    for (int q2 = 0; q2 < qw; q2++) pf *= wtot[q2];
                    excl = pf;
                }
                float a = (1.f - u_s[tid]) * excl;
                float cwv = cwl[tid] / scal[29];
                float w = scal[2]*(scal[1]*a + (1.f-scal[1])*cwv);
                wwn[tid] = w; sW2[tid] = w;
            }
            __syncthreads();

            if (wid == 0) {
                float v = wwn[lane]+wwn[lane+32]+wwn[lane+64]+wwn[lane+96];
                v = wredsum(v);
                if (lane == 0) scal[30] = v;
            }
            #pragma unroll
            for (int it = 0; it < 8; it++) {
                int idx = tid + it*NTHR;
                int n = idx>>6, w = idx&63;
                float m = sM[n*65+w];
                sM[n*65+w] = m*(1.f - wwn[n]*ers[w]) + wwn[n]*sv[389+w];
            }
            {
                int i = tid>>3, j0 = (tid&7)*16;
                float wwi = wwn[i];
                #pragma unroll
                for (int j = j0; j < j0+16; j++) {
                    float l = sL[i*129+j];
                    l = (1.f - wwi - wwn[j])*l + wwi*sP[j];
                    if (j == i) l = 0.f;
                    sL[i*129+j] = l;
                }
            }
            __syncthreads();

            if (tid < 128) sP[tid] = (1.f - scal[30])*sP[tid] + wwn[tid];
            {
                int q = tid>>9, r = (tid>>7)&3, i = tid&127;
                float f = 0.f, bk = 0.f;
                #pragma unroll 8
                for (int j = q*64; j < q*64+64; j++) {
                    float wrj = sWr[r*128+j];
                    f  += sL[i*129+j]*wrj;
                    bk += sL[j*129+i]*wrj;
                }
                fp_f[q*512 + r*128 + i] = f;
                fp_b[q*512 + r*128 + i] = bk;
            }
            __syncthreads();

            if (tid < 512) {
                fp_f[tid] += fp_f[512+tid];
                fp_b[tid] += fp_b[512+tid];
                int r = tid>>7, n = tid&127;
                float d = 0.f;
                #pragma unroll 8
                for (int w=0;w<64;w++) d += sM[n*65+w]*sv[r*64+w];
                crs[tid] = d;
            } else if (tid < 640) {
                int n = tid-512;
                float n2 = 0.f;
                #pragma unroll 8
                for (int w=0;w<64;w++){ float m=sM[n*65+w]; n2+=m*m; }
                so[n] = sqrtf(n2)+EPSF;
            }
            __syncthreads();

            if (tid < 512) {
                int r = tid>>7, n = tid&127;
                crs[tid] = expf(scal[4+r]*crs[tid]/(so[n]*scal[12+r]));
            }
            __syncthreads();

            if (wid < 4) {
                float v = crs[wid*128+lane]+crs[wid*128+32+lane]
                        + crs[wid*128+64+lane]+crs[wid*128+96+lane];
                v = wredsum(v);
                if (lane == 0) wtot[wid] = v;
            }
            __syncthreads();

            if (tid < 512) {
                int r = tid>>7;
                float cc = crs[tid] / wtot[r];
                float w = scal[16+3*r]*fp_b[tid] + scal[17+3*r]*cc + scal[18+3*r]*fp_f[tid];
                sWr[tid] = w;
            }
            __syncthreads();

            {
                int q = tid>>8, rw = tid&255, r = rw>>6, w = rw&63;
                float s = 0.f;
                #pragma unroll 8
                for (int n = q*32; n < q*32+32; n++)
                    s += sWr[r*128+n]*sM[n*65+w];
                fp_f[q*256 + rw] = s;
            }
            __syncthreads();

            if (tid < 256) {
                float s = fp_f[tid] + fp_f[256+tid] + fp_f[512+tid] + fp_f[768+tid];
                g_reads[p^1][b*256 + tid] = s;
            }
            // ---- bar_r: D-blocks arrive (then also wait below) ----
            __syncthreads();
            if (tid == 0) bar_arrive(2);
        } else if (bq < 96) {
            if (t > 0)
                out_dev(Wout, bout, out, hprev, rdold, t-1, bq-32, scr);
            if (t+1 < TT)
                a1_part(acc, xseq, Wx, Wh, hnew, t+1, bq, scr);
        } else {
            if (t+1 < TT)
                a1_part(acc, xseq, Wx, Wh, hnew, t+1, bq, scr);
        }
        // ---- bar_r: all wait for the 32 D-block arrivals ----
        if (tid == 0) bar_spin(2, sbase[2] + step1*32u);
        __syncthreads();
    }

    // final out(127): h(127) in g_h[0], reads(127) in g_reads[0]
    if (bq >= 32 && bq < 96)
        out_dev(Wout, bout, out, g_h[0], g_reads[0], 127, bq-32, scr);
}

extern "C" void kernel_launch(void* const* d_in, const int* in_sizes, int n_in,
                              void* d_out, int out_size)
{
    const float* xseq = (const float*)d_in[0];
    const float* Wx   = (const float*)d_in[1];
    const float* Wh   = (const float*)d_in[2];
    const float* bl   = (const float*)d_in[3];
    const float* Wif  = (const float*)d_in[4];
    const float* bif  = (const float*)d_in[5];
    const float* Wout = (const float*)d_in[6];
    const float* bout = (const float*)d_in[7];
    float* out = (float*)d_out;

    cudaFuncSetAttribute(dnc_kernel, cudaFuncAttributeMaxDynamicSharedMemorySize, SMEM_BYTES);
    dnc_kernel<<<NBLK, NTHR, SMEM_BYTES>>>(xseq, Wx, Wh, bl, Wif, bif, Wout, bout, out);
}